// round 11
// baseline (speedup 1.0000x reference)
#include <cuda_runtime.h>

#define BB 16
#define CC 32
#define TILE_N 64
#define TPB 64
#define NSTG 3
#define STAGE_BYTES (CC * TILE_N * 4)    // 8192
#define MAXBLK 2048
#define TPB_FB 128

// Scratch (no device allocations). g_bar self-resets -> graph-replay safe.
__device__ double g_partials[MAXBLK];
__device__ unsigned int g_bar = 0;

__device__ __forceinline__ float fast_ex2(float x){float r;asm("ex2.approx.ftz.f32 %0,%1;":"=f"(r):"f"(x));return r;}
__device__ __forceinline__ float fast_lg2(float x){float r;asm("lg2.approx.ftz.f32 %0,%1;":"=f"(r):"f"(x));return r;}

__device__ __forceinline__ unsigned smem_u32(const void* p){
    unsigned a; asm("{.reg .u64 t; cvta.to.shared.u64 t, %1; cvt.u32.u64 %0, t;}" : "=r"(a) : "l"(p)); return a;
}
__device__ __forceinline__ void mbar_init(unsigned a, unsigned cnt){
    asm volatile("mbarrier.init.shared.b64 [%0], %1;" :: "r"(a), "r"(cnt) : "memory");
}
__device__ __forceinline__ void mbar_expect_tx(unsigned a, unsigned bytes){
    asm volatile("mbarrier.arrive.expect_tx.shared.b64 _, [%0], %1;" :: "r"(a), "r"(bytes) : "memory");
}
__device__ __forceinline__ void mbar_arrive(unsigned a){
    asm volatile("mbarrier.arrive.shared.b64 _, [%0];" :: "r"(a) : "memory");
}
__device__ __forceinline__ void mbar_wait(unsigned a, unsigned ph){
    unsigned done = 0;
    while(!done){
        asm volatile("{\n\t.reg .pred p;\n\t"
                     "mbarrier.try_wait.parity.acquire.cta.shared::cta.b64 p, [%1], %2, 0x989680;\n\t"
                     "selp.b32 %0,1,0,p;\n\t}"
            : "=r"(done) : "r"(a), "r"(ph) : "memory");
    }
}
__device__ __forceinline__ void bulk_g2s(unsigned dst, const void* src, unsigned bytes, unsigned mbar){
    asm volatile("cp.async.bulk.shared::cluster.global.mbarrier::complete_tx::bytes [%0], [%1], %2, [%3];"
        :: "r"(dst), "l"(src), "r"(bytes), "r"(mbar) : "memory");
}

// ---------------- TMA-pipelined kernel: requires N % TILE_N == 0 and N/TILE_N <= MAXBLK.
__global__ void __launch_bounds__(TPB) fpce_tma(const float* __restrict__ pred,
                                                const int* __restrict__ tru,
                                                int N, float* __restrict__ out) {
    extern __shared__ float stg[];                      // NSTG stages of [CC][TILE_N]
    __shared__ unsigned long long mb_full[NSTG], mb_empty[NSTG];
    __shared__ double wsum[TPB / 32];
    __shared__ int isLast;

    const int tid = threadIdx.x;
    const int n0  = blockIdx.x * TILE_N;
    const int n   = n0 + tid;
    const float LOG2E = 1.4426950408889634f;

    unsigned stg_a = smem_u32(stg);
    unsigned full_a[NSTG], empty_a[NSTG];
#pragma unroll
    for (int s = 0; s < NSTG; s++) {
        full_a[s]  = smem_u32(&mb_full[s]);
        empty_a[s] = smem_u32(&mb_empty[s]);
    }

    if (tid == 0) {
#pragma unroll
        for (int s = 0; s < NSTG; s++) { mbar_init(full_a[s], 1); mbar_init(empty_a[s], TPB); }
    }
    __syncthreads();

    // Producer: prime the first NSTG stages (rounds 0..NSTG-1).
    if (tid == 0) {
#pragma unroll
        for (int r = 0; r < NSTG; r++) {
            mbar_expect_tx(full_a[r], STAGE_BYTES);
#pragma unroll
            for (int c = 0; c < CC; c++)
                bulk_g2s(stg_a + (unsigned)((r * CC + c) * TILE_N * 4),
                         pred + (size_t)(r * CC + c) * (size_t)N + n0,
                         TILE_N * 4, full_a[r]);
        }
    }

    // Per-thread class counts (overlaps the initial TMA latency).
    unsigned long long p0 = 0, p1 = 0, p2 = 0, p3 = 0;
#pragma unroll
    for (int b = 0; b < BB; b++) {
        const int t = tru[(size_t)b * (size_t)N + n];
        const unsigned long long inc = 1ull << ((t & 7) << 3);
        const int g = t >> 3;
        p0 += (g == 0) ? inc : 0ull; p1 += (g == 1) ? inc : 0ull;
        p2 += (g == 2) ? inc : 0ull; p3 += (g == 3) ? inc : 0ull;
    }
    float cntf[CC];
#pragma unroll
    for (int c = 0; c < 8; c++) {
        cntf[c]      = (float)((p0 >> (c * 8)) & 0xFFull);
        cntf[8 + c]  = (float)((p1 >> (c * 8)) & 0xFFull);
        cntf[16 + c] = (float)((p2 >> (c * 8)) & 0xFFull);
        cntf[24 + c] = (float)((p3 >> (c * 8)) & 0xFFull);
    }

    float thread_total = 0.0f;
    int s = 0, ph = 0;

#pragma unroll 1
    for (int b = 0; b < BB; b++) {
        mbar_wait(full_a[s], (unsigned)ph);

        const float* xs = stg + s * CC * TILE_N;
        float y[CC];
        float s0 = 0.f, s1 = 0.f, s2 = 0.f, s3 = 0.f;
#pragma unroll
        for (int c = 0; c < CC; c++) {
            y[c] = xs[c * TILE_N + tid] * LOG2E;
            const float e = fast_ex2(y[c]);
            if ((c & 3) == 0) s0 += e; else if ((c & 3) == 1) s1 += e;
            else if ((c & 3) == 2) s2 += e; else s3 += e;
        }
        const float L2 = fast_lg2((s0 + s1) + (s2 + s3));

        float a0 = 0.f, a1 = 0.f, a2 = 0.f, a3 = 0.f;
#pragma unroll
        for (int c = 0; c < CC; c++) {
            const float d = L2 - y[c];
            const float e = fast_ex2(d);
            const float t = cntf[c] * d;
            if ((c & 3) == 0) a0 = fmaf(t, e, a0); else if ((c & 3) == 1) a1 = fmaf(t, e, a1);
            else if ((c & 3) == 2) a2 = fmaf(t, e, a2); else a3 = fmaf(t, e, a3);
        }
        thread_total += (a0 + a1) + (a2 + a3);

        mbar_arrive(empty_a[s]);

        // Producer: refill this stage for round b+NSTG once all consumers drained it.
        if (tid == 0 && b + NSTG < BB) {
            mbar_wait(empty_a[s], (unsigned)ph);
            mbar_expect_tx(full_a[s], STAGE_BYTES);
            const int r = b + NSTG;
#pragma unroll
            for (int c = 0; c < CC; c++)
                bulk_g2s(stg_a + (unsigned)((s * CC + c) * TILE_N * 4),
                         pred + (size_t)(r * CC + c) * (size_t)N + n0,
                         TILE_N * 4, full_a[s]);
        }
        if (++s == NSTG) { s = 0; ph ^= 1; }
    }
    thread_total *= 0.6931471805599453f;   // ln2: log2 -> ln domain

    // ---- Reduction (double) + device-wide done-counter.
    double v = (double)thread_total;
#pragma unroll
    for (int off = 16; off > 0; off >>= 1)
        v += __shfl_down_sync(0xffffffffu, v, off);
    const int wid = tid >> 5;
    if ((tid & 31) == 0) wsum[wid] = v;
    __syncthreads();

    if (tid == 0) {
        double bsum = 0.0;
#pragma unroll
        for (int w = 0; w < TPB / 32; w++) bsum += wsum[w];
        g_partials[blockIdx.x] = bsum;
        __threadfence();
        isLast = (atomicAdd(&g_bar, 1u) == gridDim.x - 1) ? 1 : 0;
    }
    __syncthreads();

    if (isLast) {
        double t = 0.0;
        for (int i = tid; i < (int)gridDim.x; i += TPB) t += g_partials[i];
#pragma unroll
        for (int off = 16; off > 0; off >>= 1)
            t += __shfl_down_sync(0xffffffffu, t, off);
        if ((tid & 31) == 0) wsum[wid] = t;
        __syncthreads();
        if (tid == 0) {
            double total = 0.0;
#pragma unroll
            for (int w = 0; w < TPB / 32; w++) total += wsum[w];
            out[0] = (float)(total / (double)N);
            atomicExch(&g_bar, 0u);   // reset for next graph replay
        }
    }
}

// ---------------- Fallback (any N): plain LDG thread-per-n, grid-stride.
__global__ void __launch_bounds__(TPB_FB) fpce_fb(const float* __restrict__ pred,
                                                  const int* __restrict__ tru,
                                                  int N, float* __restrict__ out) {
    __shared__ double wsum[TPB_FB / 32];
    __shared__ int isLast;
    const float LOG2E = 1.4426950408889634f;
    float thread_total = 0.0f;

    for (int n = blockIdx.x * TPB_FB + threadIdx.x; n < N; n += gridDim.x * TPB_FB) {
        unsigned long long p0 = 0, p1 = 0, p2 = 0, p3 = 0;
        for (int b = 0; b < BB; b++) {
            const int t = tru[(size_t)b * (size_t)N + n];
            const unsigned long long inc = 1ull << ((t & 7) << 3);
            const int g = t >> 3;
            p0 += (g == 0) ? inc : 0ull; p1 += (g == 1) ? inc : 0ull;
            p2 += (g == 2) ? inc : 0ull; p3 += (g == 3) ? inc : 0ull;
        }
        float cntf[CC];
#pragma unroll
        for (int c = 0; c < 8; c++) {
            cntf[c]      = (float)((p0 >> (c * 8)) & 0xFFull);
            cntf[8 + c]  = (float)((p1 >> (c * 8)) & 0xFFull);
            cntf[16 + c] = (float)((p2 >> (c * 8)) & 0xFFull);
            cntf[24 + c] = (float)((p3 >> (c * 8)) & 0xFFull);
        }
#pragma unroll 1
        for (int b = 0; b < BB; b++) {
            const float* row = pred + (size_t)(b * CC) * (size_t)N + (size_t)n;
            float y[CC], ssum = 0.0f;
#pragma unroll
            for (int c = 0; c < CC; c++) y[c] = row[(size_t)c * (size_t)N] * LOG2E;
#pragma unroll
            for (int c = 0; c < CC; c++) ssum += fast_ex2(y[c]);
            const float L2 = fast_lg2(ssum);
            float acc = 0.0f;
#pragma unroll
            for (int c = 0; c < CC; c++) {
                const float d = L2 - y[c];
                acc = fmaf(cntf[c] * d, fast_ex2(d), acc);
            }
            thread_total += acc;
        }
    }
    thread_total *= 0.6931471805599453f;

    double v = (double)thread_total;
#pragma unroll
    for (int off = 16; off > 0; off >>= 1)
        v += __shfl_down_sync(0xffffffffu, v, off);
    const int wid = threadIdx.x >> 5;
    if ((threadIdx.x & 31) == 0) wsum[wid] = v;
    __syncthreads();
    if (threadIdx.x == 0) {
        double bsum = 0.0;
#pragma unroll
        for (int w = 0; w < TPB_FB / 32; w++) bsum += wsum[w];
        g_partials[blockIdx.x] = bsum;
        __threadfence();
        isLast = (atomicAdd(&g_bar, 1u) == gridDim.x - 1) ? 1 : 0;
    }
    __syncthreads();
    if (isLast) {
        double t = 0.0;
        for (int i = threadIdx.x; i < (int)gridDim.x; i += TPB_FB) t += g_partials[i];
#pragma unroll
        for (int off = 16; off > 0; off >>= 1)
            t += __shfl_down_sync(0xffffffffu, t, off);
        if ((threadIdx.x & 31) == 0) wsum[wid] = t;
        __syncthreads();
        if (threadIdx.x == 0) {
            double total = 0.0;
#pragma unroll
            for (int w = 0; w < TPB_FB / 32; w++) total += wsum[w];
            out[0] = (float)(total / (double)N);
            atomicExch(&g_bar, 0u);
        }
    }
}

extern "C" void kernel_launch(void* const* d_in, const int* in_sizes, int n_in,
                              void* d_out, int out_size) {
    const float* pred = (const float*)d_in[0];
    const int*   tru  = (const int*)d_in[1];
    float*       out  = (float*)d_out;

    const int N = in_sizes[1] / BB;   // true is (B, N)
    const int ntiles = N / TILE_N;

    if ((N % TILE_N == 0) && ntiles >= 1 && ntiles <= MAXBLK) {
        fpce_tma<<<ntiles, TPB, NSTG * STAGE_BYTES>>>(pred, tru, N, out);
    } else {
        int blocks = (N + TPB_FB - 1) / TPB_FB;
        if (blocks > MAXBLK) blocks = MAXBLK;
        if (blocks < 1) blocks = 1;
        fpce_fb<<<blocks, TPB_FB>>>(pred, tru, N, out);
    }
}

// round 12
// speedup vs baseline: 1.5272x; 1.5272x over previous
#include <cuda_runtime.h>
#include <cuda_fp16.h>

#define BB 16
#define CC 32
#define TILE_N 64
#define TPB 128
#define MAXBLK 2048
#define TPB_FB 128

// Scratch (no device allocations). g_bar self-resets -> graph-replay safe.
__device__ double g_partials[MAXBLK];
__device__ unsigned int g_bar = 0;

__device__ __forceinline__ float fast_ex2(float x){float r;asm("ex2.approx.ftz.f32 %0,%1;":"=f"(r):"f"(x));return r;}
__device__ __forceinline__ float fast_lg2(float x){float r;asm("lg2.approx.ftz.f32 %0,%1;":"=f"(r):"f"(x));return r;}

// Block-cooperative smem-staged kernel. Requires N % TILE_N == 0, N/TILE_N <= MAXBLK.
// Tile = 32 classes x 64 n (8KB), double-buffered. 128 threads: 4 x LDG.128 each
// per round (fully coalesced 512B per warp instruction). Compute: lane pair
// (lane^16) splits the 32 classes; smem columns XOR-swizzled by half to kill
// the 2-way bank conflict from the 64-word row stride.
__global__ void __launch_bounds__(TPB, 8) fpce_stage(const float* __restrict__ pred,
                                                     const int* __restrict__ tru,
                                                     int N, float* __restrict__ out) {
    __shared__ float stg[2][CC * TILE_N];
    __shared__ double wsum[TPB / 32];
    __shared__ int isLast;

    const int t    = threadIdx.x;
    const int lane = t & 31;
    const int half = (t >> 4) & 1;                 // class half (0: c 0-15, 1: c 16-31)
    const int nl   = (t >> 5) * 16 + (t & 15);     // local n (0..63)
    const int n0   = blockIdx.x * TILE_N;
    const float LOG2E = 1.4426950408889634f;

    // Per-thread smem/global geometry for the cooperative copy (4 float4 units).
    int   widx[4];      // smem word index (swizzled)
    size_t gidx[4];     // global float offset within a round's tile
#pragma unroll
    for (int k = 0; k < 4; k++) {
        const int u    = k * TPB + t;              // float4 unit 0..511
        const int c    = u >> 4;                   // row (class) 0..31
        const int off4 = (u & 15) * 4;             // column (float) 0..60
        const int col  = off4 ^ ((c >> 4) << 4);   // half-XOR swizzle
        widx[k] = c * TILE_N + col;
        gidx[k] = (size_t)c * (size_t)N + (size_t)(n0 + off4);
    }
    const int rcol = nl ^ (half << 4);             // my swizzled read column

    // ---- Prime round 0 loads, build counts while they are in flight.
    float4 r[4];
#pragma unroll
    for (int k = 0; k < 4; k++) r[k] = *(const float4*)(pred + gidx[k]);

    // Counts for my 16 classes: 8-bit fields in 2 u64.
    unsigned long long p0 = 0ull, p1 = 0ull;
#pragma unroll
    for (int b = 0; b < BB; b++) {
        const int tv = tru[(size_t)b * (size_t)N + (size_t)(n0 + nl)];
        const int lt = tv - (half << 4);
        const unsigned long long inc = 1ull << ((lt & 7) << 3);
        const bool mine = ((unsigned)lt < 16u);
        p0 += (mine && lt < 8) ? inc : 0ull;
        p1 += (mine && lt >= 8) ? inc : 0ull;
    }
    __half2 cnth[8];
#pragma unroll
    for (int i = 0; i < 2; i++) {
        const unsigned long long p = i ? p1 : p0;
#pragma unroll
        for (int j = 0; j < 4; j++) {
            const float lo = (float)((unsigned)(p >> (16 * j)) & 0xFFu);
            const float hi = (float)((unsigned)(p >> (16 * j + 8)) & 0xFFu);
            cnth[i * 4 + j] = __floats2half2_rn(lo, hi);
        }
    }

#pragma unroll
    for (int k = 0; k < 4; k++) *(float4*)&stg[0][widx[k]] = r[k];
    __syncthreads();

    float thread_total = 0.0f;

#pragma unroll 1
    for (int b = 0; b < BB; b++) {
        // Issue next round's global loads first (in flight during compute).
        if (b + 1 < BB) {
            const size_t rb = (size_t)(b + 1) * (size_t)CC * (size_t)N;
#pragma unroll
            for (int k = 0; k < 4; k++) r[k] = *(const float4*)(pred + rb + gidx[k]);
        }

        const float* xs = stg[b & 1];

        // Phase 1: partial Z over my 16 classes (conflict-free LDS).
        float y[16];
        float s0 = 0.f, s1 = 0.f, s2 = 0.f, s3 = 0.f;
#pragma unroll
        for (int j = 0; j < 16; j++) {
            y[j] = xs[(half * 16 + j) * TILE_N + rcol] * LOG2E;
            const float e = fast_ex2(y[j]);
            if ((j & 3) == 0) s0 += e; else if ((j & 3) == 1) s1 += e;
            else if ((j & 3) == 2) s2 += e; else s3 += e;
        }
        float s = (s0 + s1) + (s2 + s3);
        s += __shfl_xor_sync(0xffffffffu, s, 16);          // combine halves
        const float L2 = fast_lg2(s);

        // Phase 2: f = d * 2^d weighted by counts.
        float a0 = 0.f, a1 = 0.f, a2 = 0.f, a3 = 0.f;
#pragma unroll
        for (int j = 0; j < 16; j++) {
            const float d  = L2 - y[j];
            const float e  = fast_ex2(d);
            const float cf = (j & 1) ? __high2float(cnth[j >> 1])
                                     : __low2float(cnth[j >> 1]);
            const float tt = cf * d;
            if ((j & 3) == 0) a0 = fmaf(tt, e, a0); else if ((j & 3) == 1) a1 = fmaf(tt, e, a1);
            else if ((j & 3) == 2) a2 = fmaf(tt, e, a2); else a3 = fmaf(tt, e, a3);
        }
        thread_total += (a0 + a1) + (a2 + a3);

        // Stage next round (STS waits on its own LDG; latency hidden by compute above).
        if (b + 1 < BB) {
            float* dst = stg[(b + 1) & 1];
#pragma unroll
            for (int k = 0; k < 4; k++) *(float4*)&dst[widx[k]] = r[k];
        }
        __syncthreads();   // writes visible before next round's reads; also WAR-safe
    }
    thread_total *= 0.6931471805599453f;   // ln2: log2 -> ln domain

    // ---- Reduction (double) + device-wide done-counter.
    double v = (double)thread_total;
#pragma unroll
    for (int off = 16; off > 0; off >>= 1)
        v += __shfl_down_sync(0xffffffffu, v, off);
    const int wid = t >> 5;
    if (lane == 0) wsum[wid] = v;
    __syncthreads();

    if (t == 0) {
        double bsum = 0.0;
#pragma unroll
        for (int w = 0; w < TPB / 32; w++) bsum += wsum[w];
        g_partials[blockIdx.x] = bsum;
        __threadfence();
        isLast = (atomicAdd(&g_bar, 1u) == gridDim.x - 1) ? 1 : 0;
    }
    __syncthreads();

    if (isLast) {
        double tt = 0.0;
        for (int i = t; i < (int)gridDim.x; i += TPB) tt += g_partials[i];
#pragma unroll
        for (int off = 16; off > 0; off >>= 1)
            tt += __shfl_down_sync(0xffffffffu, tt, off);
        if (lane == 0) wsum[wid] = tt;
        __syncthreads();
        if (t == 0) {
            double total = 0.0;
#pragma unroll
            for (int w = 0; w < TPB / 32; w++) total += wsum[w];
            out[0] = (float)(total / (double)N);
            atomicExch(&g_bar, 0u);   // reset for next graph replay
        }
    }
}

// ---------------- Fallback (any N): plain LDG thread-per-n, grid-stride.
__global__ void __launch_bounds__(TPB_FB) fpce_fb(const float* __restrict__ pred,
                                                  const int* __restrict__ tru,
                                                  int N, float* __restrict__ out) {
    __shared__ double wsum[TPB_FB / 32];
    __shared__ int isLast;
    const float LOG2E = 1.4426950408889634f;
    float thread_total = 0.0f;

    for (int n = blockIdx.x * TPB_FB + threadIdx.x; n < N; n += gridDim.x * TPB_FB) {
        unsigned long long p0 = 0, p1 = 0, p2 = 0, p3 = 0;
        for (int b = 0; b < BB; b++) {
            const int t = tru[(size_t)b * (size_t)N + n];
            const unsigned long long inc = 1ull << ((t & 7) << 3);
            const int g = t >> 3;
            p0 += (g == 0) ? inc : 0ull; p1 += (g == 1) ? inc : 0ull;
            p2 += (g == 2) ? inc : 0ull; p3 += (g == 3) ? inc : 0ull;
        }
        float cntf[CC];
#pragma unroll
        for (int c = 0; c < 8; c++) {
            cntf[c]      = (float)((p0 >> (c * 8)) & 0xFFull);
            cntf[8 + c]  = (float)((p1 >> (c * 8)) & 0xFFull);
            cntf[16 + c] = (float)((p2 >> (c * 8)) & 0xFFull);
            cntf[24 + c] = (float)((p3 >> (c * 8)) & 0xFFull);
        }
#pragma unroll 1
        for (int b = 0; b < BB; b++) {
            const float* row = pred + (size_t)(b * CC) * (size_t)N + (size_t)n;
            float y[CC], ssum = 0.0f;
#pragma unroll
            for (int c = 0; c < CC; c++) y[c] = row[(size_t)c * (size_t)N] * LOG2E;
#pragma unroll
            for (int c = 0; c < CC; c++) ssum += fast_ex2(y[c]);
            const float L2 = fast_lg2(ssum);
            float acc = 0.0f;
#pragma unroll
            for (int c = 0; c < CC; c++) {
                const float d = L2 - y[c];
                acc = fmaf(cntf[c] * d, fast_ex2(d), acc);
            }
            thread_total += acc;
        }
    }
    thread_total *= 0.6931471805599453f;

    double v = (double)thread_total;
#pragma unroll
    for (int off = 16; off > 0; off >>= 1)
        v += __shfl_down_sync(0xffffffffu, v, off);
    const int wid = threadIdx.x >> 5;
    if ((threadIdx.x & 31) == 0) wsum[wid] = v;
    __syncthreads();
    if (threadIdx.x == 0) {
        double bsum = 0.0;
#pragma unroll
        for (int w = 0; w < TPB_FB / 32; w++) bsum += wsum[w];
        g_partials[blockIdx.x] = bsum;
        __threadfence();
        isLast = (atomicAdd(&g_bar, 1u) == gridDim.x - 1) ? 1 : 0;
    }
    __syncthreads();
    if (isLast) {
        double t = 0.0;
        for (int i = threadIdx.x; i < (int)gridDim.x; i += TPB_FB) t += g_partials[i];
#pragma unroll
        for (int off = 16; off > 0; off >>= 1)
            t += __shfl_down_sync(0xffffffffu, t, off);
        if ((threadIdx.x & 31) == 0) wsum[wid] = t;
        __syncthreads();
        if (threadIdx.x == 0) {
            double total = 0.0;
#pragma unroll
            for (int w = 0; w < TPB_FB / 32; w++) total += wsum[w];
            out[0] = (float)(total / (double)N);
            atomicExch(&g_bar, 0u);
        }
    }
}

extern "C" void kernel_launch(void* const* d_in, const int* in_sizes, int n_in,
                              void* d_out, int out_size) {
    const float* pred = (const float*)d_in[0];
    const int*   tru  = (const int*)d_in[1];
    float*       out  = (float*)d_out;

    const int N = in_sizes[1] / BB;   // true is (B, N)
    const int ntiles = N / TILE_N;

    if ((N % TILE_N == 0) && ntiles >= 1 && ntiles <= MAXBLK) {
        fpce_stage<<<ntiles, TPB>>>(pred, tru, N, out);
    } else {
        int blocks = (N + TPB_FB - 1) / TPB_FB;
        if (blocks > MAXBLK) blocks = MAXBLK;
        if (blocks < 1) blocks = 1;
        fpce_fb<<<blocks, TPB_FB>>>(pred, tru, N, out);
    }
}